// round 10
// baseline (speedup 1.0000x reference)
#include <cuda_runtime.h>
#include <cstdint>

#define DIM 128
#define HID 64
#define MAX_TISSUE 4096
#define TILE 16
#define NW 8     // warps per CTA
#define SXS 132  // padded float stride, X tile
#define SWS 132  // padded float stride, Wc (tf32 bits)

// scratch: projected tissue keys (+ both biases folded in)
__device__ float g_tkb[MAX_TISSUE * HID];

// ---------------------------------------------------------------------------
// Kernel A: tkb[t][h] = bt[h] + bc[h] + sum_d Wt[h][d] * tissue[t][d]
// ---------------------------------------------------------------------------
__global__ void tissue_proj_kernel(const float* __restrict__ tissue,
                                   const float* __restrict__ Wt,
                                   const float* __restrict__ bt,
                                   const float* __restrict__ bc,
                                   int n_tissue) {
    __shared__ float st[16][DIM];
    __shared__ float swt[HID][DIM + 4];
    int tid = threadIdx.x;
    int t0 = blockIdx.x * 16;

    for (int i = tid; i < HID * (DIM / 4); i += 256) {
        int h = i >> 5, c = i & 31;
        float4 v = ((const float4*)Wt)[h * 32 + c];
        *(float4*)&swt[h][c * 4] = v;
    }
    for (int i = tid; i < 16 * 32; i += 256) {
        int r = i >> 5, c = i & 31;
        float4 v = make_float4(0.f, 0.f, 0.f, 0.f);
        if (t0 + r < n_tissue) v = ((const float4*)tissue)[(size_t)(t0 + r) * 32 + c];
        *(float4*)&st[r][c * 4] = v;
    }
    __syncthreads();

    #pragma unroll
    for (int j = 0; j < 4; j++) {
        int o = tid + j * 256;
        int tl = o >> 6, h = o & 63;
        if (t0 + tl >= n_tissue) continue;
        float acc = bt[h] + bc[h];
        #pragma unroll 8
        for (int c = 0; c < 32; c++) {
            float4 w = *(const float4*)&swt[h][c * 4];
            float4 x = *(const float4*)&st[tl][c * 4];
            acc += w.x * x.x + w.y * x.y + w.z * x.z + w.w * x.w;
        }
        g_tkb[(size_t)(t0 + tl) * HID + h] = acc;
    }
}

// ---------------------------------------------------------------------------
__device__ __forceinline__ unsigned f2tf32(float x) {
    unsigned r;
    asm("cvt.rna.tf32.f32 %0, %1;" : "=r"(r) : "f"(x));
    return r;
}
__device__ __forceinline__ float tanh_ap(float x) {
    float y;
    asm("tanh.approx.f32 %0, %1;" : "=f"(y) : "f"(x));
    return y;
}
__device__ __forceinline__ void cp_async16(unsigned sdst, const void* gsrc, bool pred) {
    int sz = pred ? 16 : 0;
    asm volatile("cp.async.cg.shared.global [%0], [%1], 16, %2;\n"
                 :: "r"(sdst), "l"(gsrc), "r"(sz));
}
__device__ __forceinline__ void cp_commit() {
    asm volatile("cp.async.commit_group;\n" ::: "memory");
}
__device__ __forceinline__ void cp_wait1() {
    asm volatile("cp.async.wait_group 1;\n" ::: "memory");
}
__device__ __forceinline__ void ldm_x4(unsigned* r, unsigned saddr) {
    asm volatile("ldmatrix.sync.aligned.m8n8.x4.shared.b16 {%0,%1,%2,%3}, [%4];"
                 : "=r"(r[0]), "=r"(r[1]), "=r"(r[2]), "=r"(r[3])
                 : "r"(saddr));
}

extern __shared__ float smem[];

// ---------------------------------------------------------------------------
// Kernel B: warp-autonomous persistent kernel. Each warp owns 16-row tiles
// with its own double-buffered smem slot; NO block barriers in the mainloop.
// ---------------------------------------------------------------------------
__global__ __launch_bounds__(256, 1)
void fuse_kernel(const float* __restrict__ cellf,
                 const float* __restrict__ tissuef,
                 const int* __restrict__ c2t,
                 const float* __restrict__ Wc,
                 const float* __restrict__ attnw,
                 float* __restrict__ out,
                 int n_cell, int ntiles) {
    float*    sx  = smem;                                  // NW*2*16*SXS floats
    unsigned* swc = (unsigned*)(smem + NW * 2 * TILE * SXS); // 64*SWS tf32 bits

    int tid = threadIdx.x;
    int wid = tid >> 5, lane = tid & 31;
    int gid = lane >> 2, tig = lane & 3;
    int lml = lane & 7, lmm = lane >> 3;

    // ---- one-time staging: Wc as tf32 (all 256 threads) ----
    for (int i = tid; i < 64 * 32; i += 256) {
        int r = i >> 5, c = i & 31;
        float4 v = ((const float4*)Wc)[r * 32 + c];
        uint4 w;
        w.x = f2tf32(v.x); w.y = f2tf32(v.y); w.z = f2tf32(v.z); w.w = f2tf32(v.w);
        *(uint4*)&swc[r * SWS + c * 4] = w;
    }
    __syncthreads();   // the ONLY block barrier

    // attn weights, register-resident (cols nt*8+2tig, +1)
    float aw[8][2];
    #pragma unroll
    for (int nt = 0; nt < 8; nt++) {
        float2 v = ((const float2*)attnw)[nt * 4 + tig];
        aw[nt][0] = v.x; aw[nt][1] = v.y;
    }

    // per-warp smem slot + ldmatrix lane addresses
    float* wbuf = sx + wid * 2 * TILE * SXS;
    unsigned wbuf_u = (unsigned)__cvta_generic_to_shared(wbuf);
    unsigned swc_u  = (unsigned)__cvta_generic_to_shared(swc);
    unsigned a_off = ((unsigned)(((lmm & 1) * 8 + lml) * SXS + (lmm >> 1) * 4)) * 4u;
    unsigned b_off = swc_u + ((unsigned)(lml * SWS + lmm * 4)) * 4u;

    int stride = gridDim.x * NW;
    int t0w = blockIdx.x * NW + wid;

    // warp-scope tile issue: 16 rows x 128 floats, each lane 16 cp.async16
    auto issue_x = [&](int t, int buf) {
        unsigned dst = wbuf_u + (unsigned)(buf * TILE * SXS) * 4u
                     + (unsigned)lane * 16u;
        const float* src = cellf + (size_t)t * TILE * DIM + lane * 4;
        #pragma unroll
        for (int r = 0; r < TILE; r++) {
            int row = t * TILE + r;
            bool ok = row < n_cell;
            cp_async16(dst + (unsigned)(r * SXS) * 4u,
                       ok ? (src + (size_t)r * DIM) : cellf, ok);
        }
    };
    auto load_ids = [&](int t) -> int {
        int row = t * TILE + (lane & 15);
        return c2t[row < n_cell ? row : 0];
    };

    // prologue: tile t0w in flight
    int idc = 0;
    if (t0w < ntiles) {
        issue_x(t0w, 0);
        idc = load_ids(t0w);
    }
    cp_commit();

    int it = 0;
    for (int t = t0w; t < ntiles; t += stride, it++) {
        int buf = it & 1;
        int tn = t + stride;
        int idn = 0;
        if (tn < ntiles) {
            issue_x(tn, buf ^ 1);
            idn = load_ids(tn);
        }
        cp_commit();
        cp_wait1();           // tile t resident (t+stride may still fly)
        __syncwarp();

        // ---- issue tkb gather now; consumed after the mma phase ----
        int tlo = __shfl_sync(0xffffffffu, idc, gid);
        int thi = __shfl_sync(0xffffffffu, idc, gid + 8);
        float2 klo[8], khi[8];
        {
            const float2* plo = (const float2*)&g_tkb[(size_t)tlo * HID];
            const float2* phi = (const float2*)&g_tkb[(size_t)thi * HID];
            #pragma unroll
            for (int nt = 0; nt < 8; nt++) {
                klo[nt] = plo[nt * 4 + tig];
                khi[nt] = phi[nt * 4 + tig];
            }
        }

        // ---- Q = X @ Wc^T (acc from zero; keys added at score time) ----
        float acc[8][4];
        #pragma unroll
        for (int nt = 0; nt < 8; nt++) {
            acc[nt][0] = 0.f; acc[nt][1] = 0.f; acc[nt][2] = 0.f; acc[nt][3] = 0.f;
        }
        unsigned abase = wbuf_u + (unsigned)(buf * TILE * SXS) * 4u + a_off;
        #pragma unroll
        for (int p = 0; p < 8; p++) {
            unsigned a0[4], a1[4];
            ldm_x4(a0, abase + (unsigned)(p * 64));        // kk = 2p
            ldm_x4(a1, abase + (unsigned)(p * 64 + 32));   // kk = 2p+1
            #pragma unroll
            for (int nt = 0; nt < 8; nt++) {
                unsigned b[4];
                ldm_x4(b, b_off + (unsigned)(nt * 8 * SWS) * 4u + (unsigned)(p * 64));
                asm volatile(
                    "mma.sync.aligned.m16n8k8.row.col.f32.tf32.tf32.f32 "
                    "{%0,%1,%2,%3}, {%4,%5,%6,%7}, {%8,%9}, {%0,%1,%2,%3};\n"
                    : "+f"(acc[nt][0]), "+f"(acc[nt][1]),
                      "+f"(acc[nt][2]), "+f"(acc[nt][3])
                    : "r"(a0[0]), "r"(a0[1]), "r"(a0[2]), "r"(a0[3]),
                      "r"(b[0]), "r"(b[1]));
                asm volatile(
                    "mma.sync.aligned.m16n8k8.row.col.f32.tf32.tf32.f32 "
                    "{%0,%1,%2,%3}, {%4,%5,%6,%7}, {%8,%9}, {%0,%1,%2,%3};\n"
                    : "+f"(acc[nt][0]), "+f"(acc[nt][1]),
                      "+f"(acc[nt][2]), "+f"(acc[nt][3])
                    : "r"(a1[0]), "r"(a1[1]), "r"(a1[2]), "r"(a1[3]),
                      "r"(b[2]), "r"(b[3]));
            }
        }

        // ---- score = attn . tanh(q + key); quad reduce; gate ----
        float p0 = 0.f, p1 = 0.f;
        #pragma unroll
        for (int nt = 0; nt < 8; nt++) {
            p0 += aw[nt][0] * tanh_ap(acc[nt][0] + klo[nt].x)
                + aw[nt][1] * tanh_ap(acc[nt][1] + klo[nt].y);
            p1 += aw[nt][0] * tanh_ap(acc[nt][2] + khi[nt].x)
                + aw[nt][1] * tanh_ap(acc[nt][3] + khi[nt].y);
        }
        p0 += __shfl_xor_sync(0xffffffffu, p0, 1);
        p0 += __shfl_xor_sync(0xffffffffu, p0, 2);
        p1 += __shfl_xor_sync(0xffffffffu, p1, 1);
        p1 += __shfl_xor_sync(0xffffffffu, p1, 2);
        // every lane now holds full scores for rows gid (p0) and gid+8 (p1)
        float g0 = __fdividef(1.f, 1.f + __expf(-p0));
        float g1 = __fdividef(1.f, 1.f + __expf(-p1));

        // ---- epilogue: row j per step, lane = column; out = x + tissue*g ----
        float* bx = wbuf + buf * TILE * SXS;
        #pragma unroll
        for (int j = 0; j < TILE; j++) {
            int row = t * TILE + j;
            if (row >= n_cell) break;
            float g = (j < 8) ? __shfl_sync(0xffffffffu, g0, j * 4)
                              : __shfl_sync(0xffffffffu, g1, (j - 8) * 4);
            int tt = __shfl_sync(0xffffffffu, idc, j);
            float4 xv = *(const float4*)&bx[j * SXS + lane * 4];
            float4 tv = ((const float4*)tissuef)[(size_t)tt * 32 + lane];
            float4 o;
            o.x = fmaf(tv.x, g, xv.x);
            o.y = fmaf(tv.y, g, xv.y);
            o.z = fmaf(tv.z, g, xv.z);
            o.w = fmaf(tv.w, g, xv.w);
            ((float4*)out)[(size_t)row * 32 + lane] = o;
        }

        idc = idn;
        __syncwarp();   // all lanes done reading buf before it is refilled
    }
}

// ---------------------------------------------------------------------------
extern "C" void kernel_launch(void* const* d_in, const int* in_sizes, int n_in,
                              void* d_out, int out_size) {
    const float* cellf   = (const float*)d_in[0];
    const float* tissuef = (const float*)d_in[1];
    const int*   c2t     = (const int*)d_in[2];
    const float* Wt      = (const float*)d_in[3];
    const float* bt      = (const float*)d_in[4];
    const float* Wc      = (const float*)d_in[5];
    const float* bc      = (const float*)d_in[6];
    const float* attnw   = (const float*)d_in[7];
    float* out = (float*)d_out;

    int n_cell   = in_sizes[0] / DIM;
    int n_tissue = in_sizes[1] / DIM;
    int ntiles   = (n_cell + TILE - 1) / TILE;

    tissue_proj_kernel<<<(n_tissue + 15) / 16, 256>>>(tissuef, Wt, bt, bc, n_tissue);

    int dev = 0, sms = 148;
    cudaGetDevice(&dev);
    cudaDeviceGetAttribute(&sms, cudaDevAttrMultiProcessorCount, dev);

    size_t shmem_bytes = (size_t)(NW * 2 * TILE * SXS + 64 * SWS) * 4;
    cudaFuncSetAttribute(fuse_kernel,
                         cudaFuncAttributeMaxDynamicSharedMemorySize,
                         (int)shmem_bytes);
    int grid = sms;
    fuse_kernel<<<grid, 256, shmem_bytes>>>(cellf, tissuef, c2t, Wc, attnw,
                                            out, n_cell, ntiles);
}